// round 12
// baseline (speedup 1.0000x reference)
#include <cuda_runtime.h>
#include <cuda_bf16.h>
#include <mma.h>
#include <math.h>
#include <stdint.h>

using namespace nvcuda;

#define NTOK 4096
#define D    2048
#define DH   1024
#define NE   8
#define NI   8192
#define MAXM  4096
#define MAXM1 4104   // rows per expert incl. virtual Ce row + pad

// ---------------- device-global scratch: ~1.41 GB total (proven-safe level) ----------------
__device__ __nv_bfloat16 g_xh[(size_t)NTOK * D], g_xl[(size_t)NTOK * D];
__device__ __nv_bfloat16 g_Hh[(size_t)NE * MAXM1 * NI], g_Hl[(size_t)NE * MAXM1 * NI];
__device__ float g_Y[(size_t)NE * MAXM1 * D];
__device__ float g_Hr[(size_t)NTOK * DH];
__device__ float g_S[2 * D];
__device__ int   g_cnt[NE], g_active[NE * 2];
__device__ int   g_ptok[NE * MAXM];
__device__ int   g_pslot[NTOK * 2], g_te[NTOK * 2];
__device__ float g_tw[NTOK * 2];

// ---------------- helpers ----------------
__device__ __forceinline__ float gelu_f(float v) {
    return 0.5f * v * (1.0f + erff(v * 0.7071067811865475f));
}
__device__ __forceinline__ void bf16_split(float v, __nv_bfloat16& h, __nv_bfloat16& l) {
    h = __float2bfloat16_rn(v);
    l = __float2bfloat16_rn(v - __bfloat162float(h));
}
__device__ __forceinline__ uint32_t smem_u32(const void* p) {
    uint32_t a;
    asm("{ .reg .u64 t; cvta.to.shared.u64 t, %1; cvt.u32.u64 %0, t; }" : "=r"(a) : "l"(p));
    return a;
}
__device__ __forceinline__ void cp16(uint32_t s, const void* g) {
    asm volatile("cp.async.cg.shared.global [%0], [%1], 16;" :: "r"(s), "l"(g));
}

// ---------------- bookkeeping ----------------
__global__ void k_zero() {
    int t = threadIdx.x;
    if (t < NE)     g_cnt[t] = 0;
    if (t < NE * 2) g_active[t] = 0;
}

__global__ void k_cvt_x(const float* __restrict__ x) {
    size_t i = (size_t)blockIdx.x * blockDim.x + threadIdx.x;
    float4 v = ((const float4*)x)[i];
    __align__(8) __nv_bfloat16 hh[4], ll[4];
    bf16_split(v.x, hh[0], ll[0]); bf16_split(v.y, hh[1], ll[1]);
    bf16_split(v.z, hh[2], ll[2]); bf16_split(v.w, hh[3], ll[3]);
    *(uint2*)(g_xh + 4 * i) = *(uint2*)hh;
    *(uint2*)(g_xl + 4 * i) = *(uint2*)ll;
}

// virtual Ce row: H[slot = cnt] = gelu(b1[e])
__global__ void k_append(const float* __restrict__ b1) {
    int e = blockIdx.y;
    int i = blockIdx.x * blockDim.x + threadIdx.x;
    float v = gelu_f(b1[(size_t)e * NI + i]);
    __nv_bfloat16 h, l; bf16_split(v, h, l);
    size_t o = ((size_t)e * MAXM1 + g_cnt[e]) * NI + i;
    g_Hh[o] = h; g_Hl[o] = l;
}

// ---------------- router (fp32 SIMT — VERBATIM from the passing kernels) ----------------
__global__ __launch_bounds__(256) void k_router(const float* __restrict__ x,
                                                const float* __restrict__ rw1) {
    __shared__ float As[16][64];
    __shared__ float Bs[16][64];
    const int m0 = blockIdx.x * 64, n0 = blockIdx.y * 64;
    const int tid = threadIdx.x, tx = tid & 15, ty = tid >> 4;
    const int ar = tid >> 2, ac = (tid & 3) * 4;
    const int br = tid >> 4, bc = (tid & 15) * 4;
    const float* ap = x   + (size_t)(m0 + ar) * D + ac;
    const float* bp = rw1 + (size_t)br * DH + n0 + bc;
    float acc[4][4] = {};
    for (int k0 = 0; k0 < D; k0 += 16) {
        float4 a = *(const float4*)ap; ap += 16;
        float4 b = *(const float4*)bp; bp += (size_t)16 * DH;
        __syncthreads();
        As[ac + 0][ar] = a.x; As[ac + 1][ar] = a.y; As[ac + 2][ar] = a.z; As[ac + 3][ar] = a.w;
        *(float4*)&Bs[br][bc] = b;
        __syncthreads();
#pragma unroll
        for (int kk = 0; kk < 16; kk++) {
            float4 av = *(const float4*)&As[kk][ty * 4];
            float4 bv = *(const float4*)&Bs[kk][tx * 4];
            float a_[4] = {av.x, av.y, av.z, av.w};
            float b_[4] = {bv.x, bv.y, bv.z, bv.w};
#pragma unroll
            for (int i = 0; i < 4; i++)
#pragma unroll
                for (int j = 0; j < 4; j++) acc[i][j] += a_[i] * b_[j];
        }
    }
#pragma unroll
    for (int i = 0; i < 4; i++) {
        int gm = m0 + ty * 4 + i;
#pragma unroll
        for (int j = 0; j < 4; j++)
            g_Hr[(size_t)gm * DH + n0 + tx * 4 + j] = gelu_f(acc[i][j]);
    }
}

__global__ void k_route(const float* __restrict__ rw2) {
    int gw   = (blockIdx.x * blockDim.x + threadIdx.x) >> 5;
    int lane = threadIdx.x & 31;
    if (gw >= NTOK) return;
    const float* h = g_Hr + (size_t)gw * DH;
    float acc[8] = {};
    for (int j = lane; j < DH; j += 32) {
        float hv = h[j];
        float4 r0 = *(const float4*)(rw2 + (size_t)j * 8);
        float4 r1 = *(const float4*)(rw2 + (size_t)j * 8 + 4);
        acc[0] += hv * r0.x; acc[1] += hv * r0.y; acc[2] += hv * r0.z; acc[3] += hv * r0.w;
        acc[4] += hv * r1.x; acc[5] += hv * r1.y; acc[6] += hv * r1.z; acc[7] += hv * r1.w;
    }
#pragma unroll
    for (int e = 0; e < 8; e++)
#pragma unroll
        for (int o = 16; o; o >>= 1) acc[e] += __shfl_xor_sync(0xffffffffu, acc[e], o);
    if (lane == 0) {
        float mx = acc[0];
        for (int e = 1; e < 8; e++) mx = fmaxf(mx, acc[e]);
        float p[8], s = 0.f;
        for (int e = 0; e < 8; e++) { p[e] = expf(acc[e] - mx); s += p[e]; }
        float inv = 1.f / s;
        for (int e = 0; e < 8; e++) p[e] *= inv;
        int e0 = 0; float b0 = p[0];
        for (int e = 1; e < 8; e++) if (p[e] > b0) { b0 = p[e]; e0 = e; }
        int e1 = (e0 == 0) ? 1 : 0; float b1v = p[e1];
        for (int e = 0; e < 8; e++) if (e != e0 && p[e] > b1v) { b1v = p[e]; e1 = e; }
        int s0 = atomicAdd(&g_cnt[e0], 1);
        int s1 = atomicAdd(&g_cnt[e1], 1);
        g_ptok[e0 * MAXM + s0] = gw;
        g_ptok[e1 * MAXM + s1] = gw;
        g_pslot[gw * 2 + 0] = s0;
        g_pslot[gw * 2 + 1] = s1;
        g_te[gw * 2 + 0] = e0; g_te[gw * 2 + 1] = e1;
        g_tw[gw * 2 + 0] = b0; g_tw[gw * 2 + 1] = b1v;
        g_active[e0 * 2 + 0] = 1;
        g_active[e1 * 2 + 1] = 1;
    }
}

// ---------------- wmma bf16x3 GEMM: 512 threads, 16 warps, warp tile 32x64, CTA 128x256 ----------------
// Stage (54272 B): Ah(128x40bf16) | Al | Bh(32x264bf16) | Bl.  Three stages = 162816 B dyn smem.
#define OAH 0
#define OAL 10240
#define OBH 20480
#define OBL 37376
#define STAGEB 54272
#define SMEMSZ (3 * STAGEB)

template<int MODE>   // 1: gemm1 (A=gather(x) K=D, B=w1 [D,NI], out->H)  2: gemm2 (A=H K=NI, B=w2 [NI,D], out->Y)
__global__ void __launch_bounds__(512, 1) k_gemm(const float* __restrict__ w,
                                                 const float* __restrict__ bias) {
    constexpr int KTOT = (MODE == 1) ? D : NI;
    constexpr int NN   = (MODE == 1) ? NI : D;
    constexpr int NCH  = KTOT / 32;
    int e, mt;
    if (MODE == 1) { e = blockIdx.x >> 5; mt = blockIdx.x & 31; }
    else           { e = blockIdx.x / 33; mt = blockIdx.x % 33; }
    const int cnt = g_cnt[e];
    const int m0 = mt * 128;
    if (MODE == 1 && m0 >= cnt) return;
    if (MODE == 2 && m0 >  cnt) return;
    const int n0 = blockIdx.y * 256;
    const int tid = threadIdx.x;
    const int wid = tid >> 5;
    const int wr = wid >> 2, wc = wid & 3;     // warp tile (wr*32, wc*64)

    extern __shared__ __align__(16) char sbuf[];
    const uint32_t sbase = smem_u32(sbuf);

    // ---- A staging: thread -> (row = tid>>2, 16B slice s = tid&3) of BOTH hi/lo mats ----
    const int arow = tid >> 2, aslc = tid & 3;
    const __nv_bfloat16 *pAh, *pAl;
    if (MODE == 1) {
        int slot = m0 + arow;
        int tok = (slot < cnt) ? g_ptok[e * MAXM + slot] : 0;
        pAh = g_xh + (size_t)tok * D;
        pAl = g_xl + (size_t)tok * D;
    } else {
        int slot = m0 + arow; if (slot > cnt) slot = cnt;
        size_t ao = ((size_t)e * MAXM1 + slot) * NI;
        pAh = g_Hh + ao; pAl = g_Hl + ao;
    }
    pAh += aslc * 8; pAl += aslc * 8;          // 8 bf16 = 16 bytes per slice
    const uint32_t sA = (uint32_t)arow * 80 + (uint32_t)aslc * 16;

    // ---- B staging: thread -> (row = tid>>4, 16 floats at (tid&15)*16) ----
    const int brow = tid >> 4, bcolf = (tid & 15) * 16;
    const float* pB = w + (size_t)e * KTOT * NN + (size_t)brow * NN + n0 + bcolf;
    const uint32_t sBo = (uint32_t)brow * 528 + (uint32_t)bcolf * 2;

    auto cpA = [&](int ck, int buf) {
        uint32_t base = sbase + buf * STAGEB + sA;
        cp16(base + OAH, pAh + (size_t)ck * 32);
        cp16(base + OAL, pAl + (size_t)ck * 32);
        asm volatile("cp.async.commit_group;" ::: "memory");
    };

    float4 bpf[4];
    auto loadB = [&](int ck) {
        const float* gb = pB + (size_t)ck * 32 * NN;
#pragma unroll
        for (int i = 0; i < 4; i++) bpf[i] = *(const float4*)(gb + i * 4);
    };
    auto storeB = [&](int buf) {
        __align__(16) __nv_bfloat16 hh[16], ll[16];
#pragma unroll
        for (int q = 0; q < 4; q++) {
            float4 v = bpf[q];
            bf16_split(v.x, hh[q*4+0], ll[q*4+0]); bf16_split(v.y, hh[q*4+1], ll[q*4+1]);
            bf16_split(v.z, hh[q*4+2], ll[q*4+2]); bf16_split(v.w, hh[q*4+3], ll[q*4+3]);
        }
        char* base = sbuf + buf * STAGEB;
        *(uint4*)(base + OBH + sBo)      = ((uint4*)hh)[0];
        *(uint4*)(base + OBH + sBo + 16) = ((uint4*)hh)[1];
        *(uint4*)(base + OBL + sBo)      = ((uint4*)ll)[0];
        *(uint4*)(base + OBL + sBo + 16) = ((uint4*)ll)[1];
    };

    wmma::fragment<wmma::accumulator, 16, 16, 16, float> acc[2][4];
#pragma unroll
    for (int i = 0; i < 2; i++)
#pragma unroll
        for (int j = 0; j < 4; j++) wmma::fill_fragment(acc[i][j], 0.0f);

    // ---- prologue: stages 0 and 1 fully resident ----
    cpA(0, 0);
    loadB(0); storeB(0);
    cpA(1, 1);
    loadB(1); storeB(1);
    asm volatile("cp.async.wait_group 0;" ::: "memory");
    __syncthreads();

    // ---- main loop: ONE sync per chunk; writers target buf (c+2)%3 (last read at chunk c-1) ----
    for (int c = 0; c < NCH; c++) {
        const int buf = c % 3;
        const int wbuf = (c + 2) % 3;
        if (c + 2 < NCH) { cpA(c + 2, wbuf); loadB(c + 2); }   // LDGs overlap with mma below
        const char* st = sbuf + buf * STAGEB;
#pragma unroll
        for (int ks = 0; ks < 2; ks++) {
            wmma::fragment<wmma::matrix_a, 16, 16, 16, __nv_bfloat16, wmma::row_major> ah[2], al[2];
#pragma unroll
            for (int i = 0; i < 2; i++) {
                const char* ap = st + (wr * 32 + i * 16) * 80 + ks * 32;
                wmma::load_matrix_sync(ah[i], (const __nv_bfloat16*)(ap + OAH), 40);
                wmma::load_matrix_sync(al[i], (const __nv_bfloat16*)(ap + OAL), 40);
            }
#pragma unroll
            for (int j = 0; j < 4; j++) {
                wmma::fragment<wmma::matrix_b, 16, 16, 16, __nv_bfloat16, wmma::row_major> bh, bl;
                const char* bp = st + ks * 16 * 528 + (wc * 64 + j * 16) * 2;
                wmma::load_matrix_sync(bh, (const __nv_bfloat16*)(bp + OBH), 264);
                wmma::load_matrix_sync(bl, (const __nv_bfloat16*)(bp + OBL), 264);
#pragma unroll
                for (int i = 0; i < 2; i++) {
                    wmma::mma_sync(acc[i][j], ah[i], bh, acc[i][j]);
                    wmma::mma_sync(acc[i][j], ah[i], bl, acc[i][j]);
                    wmma::mma_sync(acc[i][j], al[i], bh, acc[i][j]);
                }
            }
        }
        if (c + 2 < NCH) storeB(wbuf);     // same safe buffer; before the barrier
        if (c + 1 < NCH) {
            if (c + 2 < NCH) asm volatile("cp.async.wait_group 1;" ::: "memory"); // A(c+1) landed
            else             asm volatile("cp.async.wait_group 0;" ::: "memory");
        }
        __syncthreads();
    }

    // ---- epilogue: all 16 disjoint warp tiles -> smem fp32 (128 x 264 pitch) -> global ----
    float* sE = (float*)sbuf;
#pragma unroll
    for (int i = 0; i < 2; i++)
#pragma unroll
        for (int j = 0; j < 4; j++)
            wmma::store_matrix_sync(sE + (wr * 32 + i * 16) * 264 + wc * 64 + j * 16,
                                    acc[i][j], 264, wmma::mem_row_major);
    __syncthreads();

    const int erow = tid >> 2, ecol = (tid & 3) * 64;
    const int row = m0 + erow;
#pragma unroll 1
    for (int q = 0; q < 64; q += 4) {
        int col = n0 + ecol + q;
        float4 v = *(float4*)(sE + erow * 264 + ecol + q);
        if (MODE == 1) {
            if (row < cnt) {
                const float* bp = bias + (size_t)e * NI + col;
                __align__(8) __nv_bfloat16 hh[4], ll[4];
                bf16_split(gelu_f(v.x + bp[0]), hh[0], ll[0]);
                bf16_split(gelu_f(v.y + bp[1]), hh[1], ll[1]);
                bf16_split(gelu_f(v.z + bp[2]), hh[2], ll[2]);
                bf16_split(gelu_f(v.w + bp[3]), hh[3], ll[3]);
                size_t o = ((size_t)e * MAXM1 + row) * NI + col;
                *(uint2*)(g_Hh + o) = *(uint2*)hh;
                *(uint2*)(g_Hl + o) = *(uint2*)ll;
            }
        } else {
            if (row <= cnt)
                *(float4*)(g_Y + ((size_t)e * MAXM1 + row) * D + col) = v;
        }
    }
}

// ---------------- S_k (b2 folded) and combine (b2 cancels in Y - Yc) ----------------
__global__ void k_s(const float* __restrict__ b2) {
    int i = blockIdx.x * blockDim.x + threadIdx.x;
    if (i >= 2 * D) return;
    int k = i / D, dd = i % D;
    float s = 0.f;
#pragma unroll
    for (int e = 0; e < NE; e++)
        if (g_active[e * 2 + k])
            s += g_Y[((size_t)e * MAXM1 + g_cnt[e]) * D + dd] + b2[(size_t)e * D + dd];
    g_S[k * D + dd] = s;
}

__global__ void k_combine(float* __restrict__ out) {
    const int t = blockIdx.x;
    const int e0 = g_te[t * 2 + 0], e1 = g_te[t * 2 + 1];
    const float w0 = g_tw[t * 2 + 0], w1 = g_tw[t * 2 + 1];
    const size_t p0 = ((size_t)e0 * MAXM1 + g_pslot[t * 2 + 0]) * D;
    const size_t p1 = ((size_t)e1 * MAXM1 + g_pslot[t * 2 + 1]) * D;
    const size_t c0 = ((size_t)e0 * MAXM1 + g_cnt[e0]) * D;
    const size_t c1 = ((size_t)e1 * MAXM1 + g_cnt[e1]) * D;
    for (int d = threadIdx.x; d < D; d += blockDim.x) {
        float v0 = g_Y[p0 + d] - g_Y[c0 + d] + g_S[d];
        float v1 = g_Y[p1 + d] - g_Y[c1 + d] + g_S[D + d];
        out[(size_t)t * D + d] = w0 * v0 + w1 * v1;
    }
}

// ---------------- launch ----------------
extern "C" void kernel_launch(void* const* d_in, const int* in_sizes, int n_in,
                              void* d_out, int out_size) {
    const float* x   = (const float*)d_in[0];
    const float* rw1 = (const float*)d_in[1];
    const float* rw2 = (const float*)d_in[2];
    const float* w1  = (const float*)d_in[3];
    const float* b1  = (const float*)d_in[4];
    const float* w2  = (const float*)d_in[5];
    const float* b2  = (const float*)d_in[6];
    float* out = (float*)d_out;

    cudaFuncSetAttribute(k_gemm<1>, cudaFuncAttributeMaxDynamicSharedMemorySize, SMEMSZ);
    cudaFuncSetAttribute(k_gemm<2>, cudaFuncAttributeMaxDynamicSharedMemorySize, SMEMSZ);

    k_cvt_x<<<(NTOK * D / 4) / 256, 256>>>(x);
    k_zero<<<1, 32>>>();
    k_router<<<dim3(NTOK / 64, DH / 64), 256>>>(x, rw1);
    k_route<<<NTOK / 8, 256>>>(rw2);
    k_append<<<dim3(NI / 256, NE), 256>>>(b1);
    k_gemm<1><<<dim3(NE * 32, NI / 256), 512, SMEMSZ>>>(w1, b1);
    k_gemm<2><<<dim3(NE * 33, D / 256), 512, SMEMSZ>>>(w2, nullptr);
    k_s<<<(2 * D) / 256, 256>>>(b2);
    k_combine<<<NTOK, 256>>>(out);
}

// round 13
// speedup vs baseline: 1.1651x; 1.1651x over previous
#include <cuda_runtime.h>
#include <cuda_bf16.h>
#include <mma.h>
#include <math.h>
#include <stdint.h>

using namespace nvcuda;

#define NTOK 4096
#define D    2048
#define DH   1024
#define NE   8
#define NI   8192
#define MAXM  4096
#define MAXM1 4104   // rows per expert incl. virtual Ce row + pad

// ---------------- device-global scratch: ~1.41 GB total (proven-safe level) ----------------
__device__ __nv_bfloat16 g_xh[(size_t)NTOK * D], g_xl[(size_t)NTOK * D];
__device__ __nv_bfloat16 g_Hh[(size_t)NE * MAXM1 * NI], g_Hl[(size_t)NE * MAXM1 * NI];
__device__ float g_Y[(size_t)NE * MAXM1 * D];
__device__ float g_Hr[(size_t)NTOK * DH];
__device__ float g_S[2 * D];
__device__ int   g_cnt[NE], g_active[NE * 2];
__device__ int   g_ptok[NE * MAXM];
__device__ int   g_pslot[NTOK * 2], g_te[NTOK * 2];
__device__ float g_tw[NTOK * 2];

// ---------------- helpers ----------------
__device__ __forceinline__ float gelu_f(float v) {
    return 0.5f * v * (1.0f + erff(v * 0.7071067811865475f));
}
__device__ __forceinline__ void bf16_split(float v, __nv_bfloat16& h, __nv_bfloat16& l) {
    h = __float2bfloat16_rn(v);
    l = __float2bfloat16_rn(v - __bfloat162float(h));
}
__device__ __forceinline__ uint32_t smem_u32(const void* p) {
    uint32_t a;
    asm("{ .reg .u64 t; cvta.to.shared.u64 t, %1; cvt.u32.u64 %0, t; }" : "=r"(a) : "l"(p));
    return a;
}
__device__ __forceinline__ void cp16(uint32_t s, const void* g) {
    asm volatile("cp.async.cg.shared.global [%0], [%1], 16;" :: "r"(s), "l"(g));
}

// ---------------- cvt_x + counter zeroing (block 0) ----------------
__global__ void k_cvt_x(const float* __restrict__ x) {
    if (blockIdx.x == 0 && threadIdx.x < 32) {
        int t = threadIdx.x;
        if (t < NE)     g_cnt[t] = 0;
        if (t < NE * 2) g_active[t] = 0;
    }
    size_t i = (size_t)blockIdx.x * blockDim.x + threadIdx.x;
    float4 v = ((const float4*)x)[i];
    __align__(8) __nv_bfloat16 hh[4], ll[4];
    bf16_split(v.x, hh[0], ll[0]); bf16_split(v.y, hh[1], ll[1]);
    bf16_split(v.z, hh[2], ll[2]); bf16_split(v.w, hh[3], ll[3]);
    *(uint2*)(g_xh + 4 * i) = *(uint2*)hh;
    *(uint2*)(g_xl + 4 * i) = *(uint2*)ll;
}

// virtual Ce row: H[slot = cnt] = gelu(b1[e])  (runs AFTER gemm1; gemm1 writes only rows < cnt)
__global__ void k_append(const float* __restrict__ b1) {
    int e = blockIdx.y;
    int i = blockIdx.x * blockDim.x + threadIdx.x;
    float v = gelu_f(b1[(size_t)e * NI + i]);
    __nv_bfloat16 h, l; bf16_split(v, h, l);
    size_t o = ((size_t)e * MAXM1 + g_cnt[e]) * NI + i;
    g_Hh[o] = h; g_Hl[o] = l;
}

// ---------------- logits + softmax + top2 (fp32, reads g_Hr) ----------------
__global__ void k_route(const float* __restrict__ rw2) {
    int gw   = (blockIdx.x * blockDim.x + threadIdx.x) >> 5;
    int lane = threadIdx.x & 31;
    if (gw >= NTOK) return;
    const float* h = g_Hr + (size_t)gw * DH;
    float acc[8] = {};
    for (int j = lane; j < DH; j += 32) {
        float hv = h[j];
        float4 r0 = *(const float4*)(rw2 + (size_t)j * 8);
        float4 r1 = *(const float4*)(rw2 + (size_t)j * 8 + 4);
        acc[0] += hv * r0.x; acc[1] += hv * r0.y; acc[2] += hv * r0.z; acc[3] += hv * r0.w;
        acc[4] += hv * r1.x; acc[5] += hv * r1.y; acc[6] += hv * r1.z; acc[7] += hv * r1.w;
    }
#pragma unroll
    for (int e = 0; e < 8; e++)
#pragma unroll
        for (int o = 16; o; o >>= 1) acc[e] += __shfl_xor_sync(0xffffffffu, acc[e], o);
    if (lane == 0) {
        float mx = acc[0];
        for (int e = 1; e < 8; e++) mx = fmaxf(mx, acc[e]);
        float p[8], s = 0.f;
        for (int e = 0; e < 8; e++) { p[e] = expf(acc[e] - mx); s += p[e]; }
        float inv = 1.f / s;
        for (int e = 0; e < 8; e++) p[e] *= inv;
        int e0 = 0; float b0 = p[0];
        for (int e = 1; e < 8; e++) if (p[e] > b0) { b0 = p[e]; e0 = e; }
        int e1 = (e0 == 0) ? 1 : 0; float b1v = p[e1];
        for (int e = 0; e < 8; e++) if (e != e0 && p[e] > b1v) { b1v = p[e]; e1 = e; }
        int s0 = atomicAdd(&g_cnt[e0], 1);
        int s1 = atomicAdd(&g_cnt[e1], 1);
        g_ptok[e0 * MAXM + s0] = gw;
        g_ptok[e1 * MAXM + s1] = gw;
        g_pslot[gw * 2 + 0] = s0;
        g_pslot[gw * 2 + 1] = s1;
        g_te[gw * 2 + 0] = e0; g_te[gw * 2 + 1] = e1;
        g_tw[gw * 2 + 0] = b0; g_tw[gw * 2 + 1] = b1v;
        g_active[e0 * 2 + 0] = 1;
        g_active[e1 * 2 + 1] = 1;
    }
}

// ---------------- wmma bf16x3 GEMM: CTA 128x256, warp 64x64, 3-stage single-sync pipeline ----------------
// MODE 0: router  Hr = gelu(x @ rw1)   K=D,  N=DH,  out fp32 g_Hr
// MODE 1: gemm1   H  = gelu(... + b1)  K=D,  N=NI,  out split g_Hh/g_Hl
// MODE 2: gemm2   Y                    K=NI, N=D,   out fp32 g_Y
// Stage (54272 B): Ah(128x40bf16) | Al | Bh(32x264bf16) | Bl.  Three stages = 162816 B dyn smem.
#define OAH 0
#define OAL 10240
#define OBH 20480
#define OBL 37376
#define STAGEB 54272
#define SMEMSZ (3 * STAGEB)

template<int MODE>
__global__ void __launch_bounds__(256, 1) k_gemm(const float* __restrict__ w,
                                                 const float* __restrict__ bias) {
    constexpr int KTOT = (MODE == 2) ? NI : D;
    constexpr int NN   = (MODE == 0) ? DH : ((MODE == 1) ? NI : D);
    constexpr int NCH  = KTOT / 32;
    int e, mt;
    if (MODE == 0)      { e = 0;               mt = blockIdx.x; }
    else if (MODE == 1) { e = blockIdx.x >> 5; mt = blockIdx.x & 31; }
    else                { e = blockIdx.x / 33; mt = blockIdx.x % 33; }
    const int cnt = (MODE == 0) ? NTOK : g_cnt[e];
    const int m0 = mt * 128;
    if (MODE == 1 && m0 >= cnt) return;
    if (MODE == 2 && m0 >  cnt) return;
    const int n0 = blockIdx.y * 256;
    const int tid = threadIdx.x;
    const int wid = tid >> 5;
    const int wr = wid >> 2, wc = wid & 3;     // warp tile (wr*64, wc*64)

    extern __shared__ __align__(16) char sbuf[];
    const uint32_t sbase = smem_u32(sbuf);

    // ---- A staging: thread -> (row = tid>>1, half = tid&1); 32 bf16 = 64B via cp.async ----
    const int arow = tid >> 1, ahalf = tid & 1;
    const __nv_bfloat16* pA;
    if (MODE == 0) {
        pA = (ahalf ? g_xl : g_xh) + (size_t)(m0 + arow) * D;
    } else if (MODE == 1) {
        int slot = m0 + arow;
        int tok = (slot < cnt) ? g_ptok[e * MAXM + slot] : 0;
        pA = (ahalf ? g_xl : g_xh) + (size_t)tok * D;
    } else {
        int slot = m0 + arow; if (slot > cnt) slot = cnt;
        pA = (ahalf ? g_Hl : g_Hh) + ((size_t)e * MAXM1 + slot) * NI;
    }
    const uint32_t sA = (ahalf ? OAL : OAH) + (uint32_t)arow * 80;

    // ---- B staging: thread -> row = tid>>3, col base (tid&7)*4 floats; 8 x float4 (i*32 apart) ----
    const int brow = tid >> 3, bcolf = (tid & 7) * 4;
    const float* pB = w + (size_t)e * KTOT * NN + (size_t)brow * NN + n0 + bcolf;
    const uint32_t sBo = (uint32_t)brow * 528 + (uint32_t)bcolf * 2;

    auto cpA = [&](int ck, int buf) {
        uint32_t d = sbase + buf * STAGEB + sA;
        const char* g = (const char*)(pA + (size_t)ck * 32);
        cp16(d, g); cp16(d + 16, g + 16); cp16(d + 32, g + 32); cp16(d + 48, g + 48);
        asm volatile("cp.async.commit_group;" ::: "memory");
    };

    float4 bpf[8];
    auto loadB = [&](int ck) {
        const float* gb = pB + (size_t)ck * 32 * NN;
#pragma unroll
        for (int i = 0; i < 8; i++) bpf[i] = *(const float4*)(gb + i * 32);
    };
    auto storeB = [&](int buf) {
        char* base = sbuf + buf * STAGEB;
#pragma unroll
        for (int i = 0; i < 8; i++) {
            float4 v = bpf[i];
            __align__(8) __nv_bfloat16 hh[4], ll[4];
            bf16_split(v.x, hh[0], ll[0]); bf16_split(v.y, hh[1], ll[1]);
            bf16_split(v.z, hh[2], ll[2]); bf16_split(v.w, hh[3], ll[3]);
            uint32_t off = sBo + (uint32_t)i * 64;   // 32 floats -> 64 bytes bf16
            *(uint2*)(base + OBH + off) = *(uint2*)hh;
            *(uint2*)(base + OBL + off) = *(uint2*)ll;
        }
    };

    wmma::fragment<wmma::accumulator, 16, 16, 16, float> acc[4][4];
#pragma unroll
    for (int i = 0; i < 4; i++)
#pragma unroll
        for (int j = 0; j < 4; j++) wmma::fill_fragment(acc[i][j], 0.0f);

    // ---- prologue: stages 0 and 1 fully resident ----
    cpA(0, 0);
    loadB(0); storeB(0);
    cpA(1, 1);
    loadB(1); storeB(1);
    asm volatile("cp.async.wait_group 0;" ::: "memory");
    __syncthreads();

    // ---- main loop: ONE sync per chunk; writers target buf (c+2)%3 (last read at chunk c-1) ----
    for (int c = 0; c < NCH; c++) {
        const int buf = c % 3;
        const int wbuf = (c + 2) % 3;
        if (c + 2 < NCH) { cpA(c + 2, wbuf); loadB(c + 2); }   // LDGs overlap with mma below
        const char* st = sbuf + buf * STAGEB;
#pragma unroll
        for (int ks = 0; ks < 2; ks++) {
            wmma::fragment<wmma::matrix_a, 16, 16, 16, __nv_bfloat16, wmma::row_major> ah[4], al[4];
#pragma unroll
            for (int i = 0; i < 4; i++) {
                const char* ap = st + (wr * 64 + i * 16) * 80 + ks * 32;
                wmma::load_matrix_sync(ah[i], (const __nv_bfloat16*)(ap + OAH), 40);
                wmma::load_matrix_sync(al[i], (const __nv_bfloat16*)(ap + OAL), 40);
            }
#pragma unroll
            for (int j = 0; j < 4; j++) {
                wmma::fragment<wmma::matrix_b, 16, 16, 16, __nv_bfloat16, wmma::row_major> bh, bl;
                const char* bp = st + ks * 16 * 528 + (wc * 64 + j * 16) * 2;
                wmma::load_matrix_sync(bh, (const __nv_bfloat16*)(bp + OBH), 264);
                wmma::load_matrix_sync(bl, (const __nv_bfloat16*)(bp + OBL), 264);
#pragma unroll
                for (int i = 0; i < 4; i++) {
                    wmma::mma_sync(acc[i][j], ah[i], bh, acc[i][j]);
                    wmma::mma_sync(acc[i][j], ah[i], bl, acc[i][j]);
                    wmma::mma_sync(acc[i][j], al[i], bh, acc[i][j]);
                }
            }
        }
        if (c + 2 < NCH) storeB(wbuf);     // same safe buffer; before the barrier
        if (c + 1 < NCH) {
            if (c + 2 < NCH) asm volatile("cp.async.wait_group 1;" ::: "memory"); // A(c+1) landed
            else             asm volatile("cp.async.wait_group 0;" ::: "memory");
        }
        __syncthreads();
    }

    // ---- epilogue via smem fp32 (128 x 136 pitch), two column halves of 128 ----
    float* sE = (float*)sbuf;
    const int erow = tid >> 1, ecol = (tid & 1) * 64;
#pragma unroll 1
    for (int h = 0; h < 2; h++) {
        __syncthreads();
        if ((wc >> 1) == h) {
#pragma unroll
            for (int i = 0; i < 4; i++)
#pragma unroll
                for (int j = 0; j < 4; j++)
                    wmma::store_matrix_sync(sE + (wr * 64 + i * 16) * 136 + (wc & 1) * 64 + j * 16,
                                            acc[i][j], 136, wmma::mem_row_major);
        }
        __syncthreads();
        const int row = m0 + erow;
#pragma unroll
        for (int q = 0; q < 64; q += 4) {
            int col = n0 + h * 128 + ecol + q;
            float4 v = *(float4*)(sE + erow * 136 + ecol + q);
            if (MODE == 0) {
                float4 o = { gelu_f(v.x), gelu_f(v.y), gelu_f(v.z), gelu_f(v.w) };
                *(float4*)(g_Hr + (size_t)row * DH + col) = o;
            } else if (MODE == 1) {
                if (row < cnt) {
                    const float* bp = bias + (size_t)e * NI + col;
                    __align__(8) __nv_bfloat16 hh[4], ll[4];
                    bf16_split(gelu_f(v.x + bp[0]), hh[0], ll[0]);
                    bf16_split(gelu_f(v.y + bp[1]), hh[1], ll[1]);
                    bf16_split(gelu_f(v.z + bp[2]), hh[2], ll[2]);
                    bf16_split(gelu_f(v.w + bp[3]), hh[3], ll[3]);
                    size_t o = ((size_t)e * MAXM1 + row) * NI + col;
                    *(uint2*)(g_Hh + o) = *(uint2*)hh;
                    *(uint2*)(g_Hl + o) = *(uint2*)ll;
                }
            } else {
                if (row <= cnt)
                    *(float4*)(g_Y + ((size_t)e * MAXM1 + row) * D + col) = v;
            }
        }
    }
}

// ---------------- S_k (b2 folded) and combine (b2 cancels in Y - Yc) ----------------
__global__ void k_s(const float* __restrict__ b2) {
    int i = blockIdx.x * blockDim.x + threadIdx.x;
    if (i >= 2 * D) return;
    int k = i / D, dd = i % D;
    float s = 0.f;
#pragma unroll
    for (int e = 0; e < NE; e++)
        if (g_active[e * 2 + k])
            s += g_Y[((size_t)e * MAXM1 + g_cnt[e]) * D + dd] + b2[(size_t)e * D + dd];
    g_S[k * D + dd] = s;
}

__global__ void k_combine(float* __restrict__ out) {
    const int t = blockIdx.x;
    const int e0 = g_te[t * 2 + 0], e1 = g_te[t * 2 + 1];
    const float w0 = g_tw[t * 2 + 0], w1 = g_tw[t * 2 + 1];
    const size_t p0 = ((size_t)e0 * MAXM1 + g_pslot[t * 2 + 0]) * D;
    const size_t p1 = ((size_t)e1 * MAXM1 + g_pslot[t * 2 + 1]) * D;
    const size_t c0 = ((size_t)e0 * MAXM1 + g_cnt[e0]) * D;
    const size_t c1 = ((size_t)e1 * MAXM1 + g_cnt[e1]) * D;
    for (int d = threadIdx.x; d < D; d += blockDim.x) {
        float v0 = g_Y[p0 + d] - g_Y[c0 + d] + g_S[d];
        float v1 = g_Y[p1 + d] - g_Y[c1 + d] + g_S[D + d];
        out[(size_t)t * D + d] = w0 * v0 + w1 * v1;
    }
}

// ---------------- launch: gemm1 at user-launch position 4 (observed ncu capture slot) ----------------
extern "C" void kernel_launch(void* const* d_in, const int* in_sizes, int n_in,
                              void* d_out, int out_size) {
    const float* x   = (const float*)d_in[0];
    const float* rw1 = (const float*)d_in[1];
    const float* rw2 = (const float*)d_in[2];
    const float* w1  = (const float*)d_in[3];
    const float* b1  = (const float*)d_in[4];
    const float* w2  = (const float*)d_in[5];
    const float* b2  = (const float*)d_in[6];
    float* out = (float*)d_out;

    cudaFuncSetAttribute(k_gemm<0>, cudaFuncAttributeMaxDynamicSharedMemorySize, SMEMSZ);
    cudaFuncSetAttribute(k_gemm<1>, cudaFuncAttributeMaxDynamicSharedMemorySize, SMEMSZ);
    cudaFuncSetAttribute(k_gemm<2>, cudaFuncAttributeMaxDynamicSharedMemorySize, SMEMSZ);

    k_cvt_x<<<(NTOK * D / 4) / 256, 256>>>(x);                        // 1 (also zeroes counters)
    k_gemm<0><<<dim3(NTOK / 128, DH / 256), 256, SMEMSZ>>>(rw1, nullptr); // 2 router matmul
    k_route<<<NTOK / 8, 256>>>(rw2);                                  // 3
    k_gemm<1><<<dim3(NE * 32, NI / 256), 256, SMEMSZ>>>(w1, b1);      // 4  <- ncu capture slot
    k_append<<<dim3(NI / 256, NE), 256>>>(b1);                        // 5 (before gemm2; writes row cnt)
    k_gemm<2><<<dim3(NE * 33, D / 256), 256, SMEMSZ>>>(w2, nullptr);  // 6
    k_s<<<(2 * D) / 256, 256>>>(b2);                                  // 7
    k_combine<<<NTOK, 256>>>(out);                                    // 8
}